// round 15
// baseline (speedup 1.0000x reference)
// ROIMaskHead fp16 pipeline v5: fused deconv(2x2,s2)+relu+1x1-mask kernel
// (z stays in smem), conv chain unchanged from v4 (at mma.sync ceiling).
#include <cuda_runtime.h>
#include <cuda_fp16.h>
#include <cstdint>

#define NROI 1024
#define M_TOT (NROI * 196)          // 200704
#define KTOT  2304
#define WLSTRIDE (256 * KTOT)

// Device-global scratch (allocation-free per harness rules)
__device__ __half g_h0[M_TOT * 256];
__device__ __half g_h1[M_TOT * 256];
__device__ __half g_wTh[4 * 256 * KTOT];     // conv W [layer][co][k]
__device__ __half g_wdTh[4 * 256 * 256];     // deconv W [parity][co][ci]
__device__ __half g_wmTh[80 * 256];          // mask W [cls][ci]

// ---------------------------------------------------------------------------
__device__ __forceinline__ uint32_t smem_u32(const void* p) {
    uint32_t a;
    asm("{ .reg .u64 t; cvta.to.shared.u64 t, %1; cvt.u32.u64 %0, t; }"
        : "=r"(a) : "l"(p));
    return a;
}
__device__ __forceinline__ void cp16(uint32_t dst, const void* src, uint32_t bytes) {
    asm volatile("cp.async.cg.shared.global [%0], [%1], 16, %2;"
                 :: "r"(dst), "l"(src), "r"(bytes) : "memory");
}
#define LDSM4(r0, r1, r2, r3, addr) \
    asm volatile("ldmatrix.sync.aligned.m8n8.x4.shared.b16 {%0,%1,%2,%3}, [%4];" \
                 : "=r"(r0), "=r"(r1), "=r"(r2), "=r"(r3) : "r"(addr))

__device__ __forceinline__ void mma_f16(float c[4], const uint32_t a[4],
                                        uint32_t b0, uint32_t b1) {
    asm volatile(
        "mma.sync.aligned.m16n8k16.row.col.f32.f16.f16.f32 "
        "{%0,%1,%2,%3}, {%4,%5,%6,%7}, {%8,%9}, {%0,%1,%2,%3};"
        : "+f"(c[0]), "+f"(c[1]), "+f"(c[2]), "+f"(c[3])
        : "r"(a[0]), "r"(a[1]), "r"(a[2]), "r"(a[3]), "r"(b0), "r"(b1));
}

// ---------------------------------------------------------------------------
// Prep kernels (unchanged)
// ---------------------------------------------------------------------------
__global__ __launch_bounds__(256)
void f2h_fp16(const float* __restrict__ in, __half* __restrict__ out)
{
    long i = (long)(blockIdx.x * 256 + threadIdx.x) * 8;
    float4 v0 = *(const float4*)(in + i);
    float4 v1 = *(const float4*)(in + i + 4);
    __half2 h[4];
    h[0] = __floats2half2_rn(v0.x, v0.y);
    h[1] = __floats2half2_rn(v0.z, v0.w);
    h[2] = __floats2half2_rn(v1.x, v1.y);
    h[3] = __floats2half2_rn(v1.z, v1.w);
    *(uint4*)(out + i) = *(uint4*)h;
}

__global__ __launch_bounds__(256)
void transpose_w_fp16(const float* __restrict__ Wc, __half* __restrict__ wTh)
{
    __shared__ float ts[32][33];
    const int l  = blockIdx.z;
    const int kq = blockIdx.y;
    const int ci0 = (blockIdx.x >> 3) * 32;
    const int co0 = (blockIdx.x & 7) * 32;
    const int tx = threadIdx.x & 31, ty = threadIdx.x >> 5;
#pragma unroll
    for (int i = ty; i < 32; i += 8)
        ts[i][tx] = Wc[((l * 9 + kq) * 256 + ci0 + i) * 256 + co0 + tx];
    __syncthreads();
#pragma unroll
    for (int i = ty; i < 32; i += 8)
        wTh[(long)(l * 256 + co0 + i) * KTOT + kq * 256 + ci0 + tx] =
            __float2half_rn(ts[tx][i]);
}

__global__ __launch_bounds__(256)
void transpose_wd_fp16(const float* __restrict__ Wt, __half* __restrict__ wdTh)
{
    __shared__ float ts[32][33];
    const int ab  = blockIdx.z;
    const int ci0 = (blockIdx.x >> 3) * 32;
    const int co0 = (blockIdx.x & 7) * 32;
    const int tx = threadIdx.x & 31, ty = threadIdx.x >> 5;
    const float* src = Wt + (3 - ab) * 65536;   // Wt[1-a][1-b] (proven in R1)
#pragma unroll
    for (int i = ty; i < 32; i += 8)
        ts[i][tx] = src[(ci0 + i) * 256 + co0 + tx];
    __syncthreads();
#pragma unroll
    for (int i = ty; i < 32; i += 8)
        wdTh[ab * 65536 + (co0 + i) * 256 + ci0 + tx] = __float2half_rn(ts[tx][i]);
}

__global__ __launch_bounds__(256)
void transpose_wm_fp16(const float* __restrict__ Wm, __half* __restrict__ wmTh)
{
    int i = blockIdx.x * 256 + threadIdx.x;
    if (i < 80 * 256) {
        int cls = i >> 8, ci = i & 255;
        wmTh[i] = __float2half_rn(Wm[ci * 80 + cls]);
    }
}

// ---------------------------------------------------------------------------
// Conv 3x3 SAME (256->256) + bias + ReLU, fp16 mma.m16n8k16.
// UNCHANGED from v4 (at mma.sync issue ceiling): 4-stage cp.async, 1 sync/iter.
// ---------------------------------------------------------------------------
#define HSTAGE (128 * 40 * 2)                // 10240 B per tile (A or B)
#define NSTAGE 4
#define STG_BYTES (2 * HSTAGE)               // A+B per stage = 20480
#define SMEM_CONVH (NSTAGE * STG_BYTES + 1024)   // 82944 B

__global__ __launch_bounds__(256, 2)
void conv3x3_fp16(const __half* __restrict__ in,
                  const __half* __restrict__ wTh,
                  const float* __restrict__ bias,
                  __half* __restrict__ out)
{
    extern __shared__ char smem[];
    const uint32_t sb = smem_u32(smem);
    float* bias_s = (float*)(smem + NSTAGE * STG_BYTES);

    const int t = threadIdx.x, wid = t >> 5, lane = t & 31;
    const int bid = blockIdx.x;
    const int m0 = (bid >> 1) * 128;
    const int n0 = (bid & 1) * 128;
    const int warpM = (wid & 1) * 64;
    const int warpN = (wid >> 1) * 32;

    if (t < 32) ((float4*)bias_s)[t] = ((const float4*)(bias + n0))[t];

    int ahh[2], aww[2]; long abase[2];
    uint32_t adst[2], bdst[2];
    const __half* bsrc[2];
#pragma unroll
    for (int s = 0; s < 2; ++s) {
        int id  = t + s * 256;
        int row = id >> 2;
        int cq  = id & 3;
        int m = m0 + row;
        int n = m / 196;
        int pp = m - n * 196;
        int hh = pp / 14;
        ahh[s] = hh; aww[s] = pp - hh * 14;
        abase[s] = (long)n * 50176 + cq * 8;
        adst[s] = sb + row * 80 + cq * 16;
        bsrc[s] = wTh + (long)(n0 + row) * KTOT + cq * 8;
        bdst[s] = sb + HSTAGE + row * 80 + cq * 16;
    }

    float c[4][4][4];
#pragma unroll
    for (int i = 0; i < 4; ++i)
#pragma unroll
        for (int j = 0; j < 4; ++j)
#pragma unroll
            for (int q = 0; q < 4; ++q) c[i][j][q] = 0.f;

    auto load_tile = [&](int kt, int p) {
        const int kq = kt >> 3, ci0 = (kt & 7) << 5;
        const int kh = kq / 3, kw = kq - kh * 3;
        const uint32_t off = p * STG_BYTES;
#pragma unroll
        for (int s = 0; s < 2; ++s) {
            int ih = ahh[s] + kh - 1, iw = aww[s] + kw - 1;
            bool ok = ((unsigned)ih < 14u) & ((unsigned)iw < 14u);
            int ihc = ok ? ih : 0, iwc = ok ? iw : 0;
            cp16(adst[s] + off, in + abase[s] + (ihc * 14 + iwc) * 256 + ci0,
                 ok ? 16u : 0u);
        }
#pragma unroll
        for (int s = 0; s < 2; ++s)
            cp16(bdst[s] + off, bsrc[s] + kt * 32, 16u);
        asm volatile("cp.async.commit_group;" ::: "memory");
    };

    const int lr = (lane & 7) + ((lane >> 3) & 1) * 8;
    const int lk = (lane >> 4) * 8;

    load_tile(0, 0);
    load_tile(1, 1);
    load_tile(2, 2);

    for (int kt = 0; kt < 72; ++kt) {
        const int p = kt & (NSTAGE - 1);
        asm volatile("cp.async.wait_group %0;" :: "n"(NSTAGE - 2) : "memory");
        __syncthreads();

        const uint32_t Ab = sb + p * STG_BYTES;
        const uint32_t Bb = Ab + HSTAGE;
#pragma unroll
        for (int ks = 0; ks < 2; ++ks) {
            const int kc = ks * 16 + lk;
            uint32_t a[4][4], bq[2][4];
#pragma unroll
            for (int i = 0; i < 4; ++i)
                LDSM4(a[i][0], a[i][1], a[i][2], a[i][3],
                      Ab + (warpM + i * 16 + lr) * 80 + kc * 2);
#pragma unroll
            for (int j2 = 0; j2 < 2; ++j2)
                LDSM4(bq[j2][0], bq[j2][1], bq[j2][2], bq[j2][3],
                      Bb + (warpN + j2 * 16 + lr) * 80 + kc * 2);
#pragma unroll
            for (int i = 0; i < 4; ++i)
#pragma unroll
                for (int j = 0; j < 4; ++j) {
                    const int j2 = j >> 1, hi = j & 1;
                    mma_f16(c[i][j], a[i], bq[j2][hi], bq[j2][hi + 2]);
                }
        }
        if (kt + NSTAGE - 1 < 72)
            load_tile(kt + NSTAGE - 1, (kt + NSTAGE - 1) & (NSTAGE - 1));
    }

#pragma unroll
    for (int j = 0; j < 4; ++j) {
        const int col = warpN + j * 8 + (lane & 3) * 2;
        const float b0 = bias_s[col], b1 = bias_s[col + 1];
#pragma unroll
        for (int i = 0; i < 4; ++i) {
            long r0 = m0 + warpM + i * 16 + (lane >> 2);
            __half2 h0 = __floats2half2_rn(fmaxf(c[i][j][0] + b0, 0.f),
                                           fmaxf(c[i][j][1] + b1, 0.f));
            __half2 h1 = __floats2half2_rn(fmaxf(c[i][j][2] + b0, 0.f),
                                           fmaxf(c[i][j][3] + b1, 0.f));
            *(__half2*)&out[(r0 << 8) + n0 + col]       = h0;
            *(__half2*)&out[((r0 + 8) << 8) + n0 + col] = h1;
        }
    }
}

// ---------------------------------------------------------------------------
// Fused deconv(2x2,s2)+relu + 1x1 mask, fp16 mma throughout, z in SMEM.
// Phase 1: z[64,256] = relu(y[64,256] @ wdT[ab]^T + bt)  (BM=64, BN=256)
// Phase 2: out[64,80] = z @ wmT^T + bm   (cls padded to 96)
// Smem: [0,51200) 2x(A 5120 + B 20480) stages (wm overlays after phase 1),
//       [51200,84992) z 64x264h pitch (528B rows, conflict-free ldmatrix),
//       [84992,86016) bt f32, [86016,86400) bm f32 (96, zero-padded).
// ---------------------------------------------------------------------------
#define DA_BYTES 5120
#define DSTG     25600
#define ZOFF     51200
#define ZPITCHB  528
#define BTOFF    84992
#define BMOFF    86016
#define SMEM_FUSED 86400

__global__ __launch_bounds__(256, 2)
void deconv_mask_fp16(const __half* __restrict__ y,
                      const __half* __restrict__ wdTh,
                      const float* __restrict__ bt,
                      const __half* __restrict__ wmTh,
                      const float* __restrict__ bm,
                      float* __restrict__ out)
{
    extern __shared__ char smem[];
    const uint32_t sb = smem_u32(smem);
    float* bt_s = (float*)(smem + BTOFF);
    float* bm_s = (float*)(smem + BMOFF);

    const int t = threadIdx.x, wid = t >> 5, lane = t & 31;
    const int pix0 = blockIdx.x * 64;
    const int ab = blockIdx.y;
    const int aa = ab >> 1, bb = ab & 1;
    const int warpN = wid * 32;              // phase 1: 1M x 8N

    if (t < 64) ((float4*)bt_s)[t] = ((const float4*)bt)[t];
    if (t < 96) bm_s[t] = (t < 80) ? bm[t] : 0.f;

    // phase-1 load mapping: A 1 chunk/thread, B 4 chunks/thread
    const int arow = t >> 2, acq = t & 3;
    const __half* asrc = y + (long)(pix0 + arow) * 256 + acq * 8;
    const uint32_t adst = sb + arow * 80 + acq * 16;
    uint32_t bdst[4];
    const __half* bsrc[4];
#pragma unroll
    for (int s = 0; s < 4; ++s) {
        int id  = t + s * 256;
        int row = id >> 2;
        int cq  = id & 3;
        bsrc[s] = wdTh + ab * 65536 + row * 256 + cq * 8;
        bdst[s] = sb + DA_BYTES + row * 80 + cq * 16;
    }

    float c[4][4][4];
#pragma unroll
    for (int i = 0; i < 4; ++i)
#pragma unroll
        for (int j = 0; j < 4; ++j)
#pragma unroll
            for (int q = 0; q < 4; ++q) c[i][j][q] = 0.f;

    auto load_tile = [&](int kt, int p) {
        cp16(adst + p * DSTG, asrc + kt * 32, 16u);
#pragma unroll
        for (int s = 0; s < 4; ++s)
            cp16(bdst[s] + p * DSTG, bsrc[s] + kt * 32, 16u);
        asm volatile("cp.async.commit_group;" ::: "memory");
    };

    const int lr = (lane & 7) + ((lane >> 3) & 1) * 8;
    const int lk = (lane >> 4) * 8;

    load_tile(0, 0);

    for (int kt = 0; kt < 8; ++kt) {
        const int p = kt & 1;
        if (kt < 7) {
            load_tile(kt + 1, p ^ 1);
            asm volatile("cp.async.wait_group 1;" ::: "memory");
        } else {
            asm volatile("cp.async.wait_group 0;" ::: "memory");
        }
        __syncthreads();

        const uint32_t Ab = sb + p * DSTG;
        const uint32_t Bb = Ab + DA_BYTES;
#pragma unroll
        for (int ks = 0; ks < 2; ++ks) {
            const int kc = ks * 16 + lk;
            uint32_t a[4][4], bq[2][4];
#pragma unroll
            for (int i = 0; i < 4; ++i)
                LDSM4(a[i][0], a[i][1], a[i][2], a[i][3],
                      Ab + (i * 16 + lr) * 80 + kc * 2);
#pragma unroll
            for (int j2 = 0; j2 < 2; ++j2)
                LDSM4(bq[j2][0], bq[j2][1], bq[j2][2], bq[j2][3],
                      Bb + (warpN + j2 * 16 + lr) * 80 + kc * 2);
#pragma unroll
            for (int i = 0; i < 4; ++i)
#pragma unroll
                for (int j = 0; j < 4; ++j) {
                    const int j2 = j >> 1, hi = j & 1;
                    mma_f16(c[i][j], a[i], bq[j2][hi], bq[j2][hi + 2]);
                }
        }
        __syncthreads();
    }
    // NOTE: the trailing __syncthreads above means all warps are done with the
    // B stages -> safe to overlay wm there now.

    // z -> smem (bias + relu), and stage wm (96x264h, pad rows zeroed)
    {
        char* zbase = smem + ZOFF;
#pragma unroll
        for (int j = 0; j < 4; ++j) {
            const int col = warpN + j * 8 + (lane & 3) * 2;
            const float b0 = bt_s[col], b1 = bt_s[col + 1];
#pragma unroll
            for (int i = 0; i < 4; ++i) {
                int r0 = i * 16 + (lane >> 2);
                __half2 h0 = __floats2half2_rn(fmaxf(c[i][j][0] + b0, 0.f),
                                               fmaxf(c[i][j][1] + b1, 0.f));
                __half2 h1 = __floats2half2_rn(fmaxf(c[i][j][2] + b0, 0.f),
                                               fmaxf(c[i][j][3] + b1, 0.f));
                *(__half2*)(zbase + r0 * ZPITCHB + col * 2)       = h0;
                *(__half2*)(zbase + (r0 + 8) * ZPITCHB + col * 2) = h1;
            }
        }
        // wm: 80 rows x 32 chunks = 2560 -> 10 per thread
#pragma unroll
        for (int s = 0; s < 10; ++s) {
            int id  = t + s * 256;
            int row = id >> 5;
            int cq  = id & 31;
            cp16(sb + row * ZPITCHB + cq * 16, wmTh + row * 256 + cq * 8, 16u);
        }
        asm volatile("cp.async.commit_group;" ::: "memory");
        // zero pad rows 80..95 (16 rows x 528B = 2112 words)
        uint32_t* pad = (uint32_t*)(smem + 80 * ZPITCHB);
        for (int idx = t; idx < 2112; idx += 256) pad[idx] = 0u;
        asm volatile("cp.async.wait_group 0;" ::: "memory");
    }
    __syncthreads();

    // phase 2: out[64, 96pad] = z @ wm^T ; 8 warps = 4M(16) x 2N(48)
    const int warpM2 = (wid & 3) * 16;
    const int warpN2 = (wid >> 2) * 48;
    float c2[6][4];
#pragma unroll
    for (int j = 0; j < 6; ++j)
#pragma unroll
        for (int q = 0; q < 4; ++q) c2[j][q] = 0.f;

    const uint32_t Zb = sb + ZOFF;
#pragma unroll
    for (int ks = 0; ks < 16; ++ks) {
        const int kc = ks * 16 + lk;
        uint32_t a2[4], bq2[3][4];
        LDSM4(a2[0], a2[1], a2[2], a2[3],
              Zb + (warpM2 + lr) * ZPITCHB + kc * 2);
#pragma unroll
        for (int j2 = 0; j2 < 3; ++j2)
            LDSM4(bq2[j2][0], bq2[j2][1], bq2[j2][2], bq2[j2][3],
                  sb + (warpN2 + j2 * 16 + lr) * ZPITCHB + kc * 2);
#pragma unroll
        for (int j = 0; j < 6; ++j) {
            const int j2 = j >> 1, hi = j & 1;
            mma_f16(c2[j], a2, bq2[j2][hi], bq2[j2][hi + 2]);
        }
    }

    // scatter to out [n,28,28,80]
    int pixA = pix0 + warpM2 + (lane >> 2);
    int pixB = pixA + 8;
    int nA = pixA / 196, pA = pixA - nA * 196, iiA = pA / 14, jjA = pA - iiA * 14;
    int nB = pixB / 196, pB = pixB - nB * 196, iiB = pB / 14, jjB = pB - iiB * 14;
    float* opA = out + ((long)(nA * 28 + iiA * 2 + aa) * 28 + jjA * 2 + bb) * 80;
    float* opB = out + ((long)(nB * 28 + iiB * 2 + aa) * 28 + jjB * 2 + bb) * 80;

#pragma unroll
    for (int j = 0; j < 6; ++j) {
        int col = warpN2 + j * 8 + (lane & 3) * 2;
        if (col < 80) {
            float b0 = bm_s[col], b1 = bm_s[col + 1];
            *(float2*)&opA[col] = make_float2(c2[j][0] + b0, c2[j][1] + b1);
            *(float2*)&opB[col] = make_float2(c2[j][2] + b0, c2[j][3] + b1);
        }
    }
}

// ---------------------------------------------------------------------------
extern "C" void kernel_launch(void* const* d_in, const int* in_sizes, int n_in,
                              void* d_out, int out_size)
{
    const float* x  = (const float*)d_in[0];
    const float* Wc = (const float*)d_in[1];
    const float* bc = (const float*)d_in[2];
    const float* Wt = (const float*)d_in[3];
    const float* bt = (const float*)d_in[4];
    const float* Wm = (const float*)d_in[5];
    const float* bm = (const float*)d_in[6];
    float* out = (float*)d_out;

    __half *h0, *h1, *wTh, *wdTh, *wmTh;
    cudaGetSymbolAddress((void**)&h0,   g_h0);
    cudaGetSymbolAddress((void**)&h1,   g_h1);
    cudaGetSymbolAddress((void**)&wTh,  g_wTh);
    cudaGetSymbolAddress((void**)&wdTh, g_wdTh);
    cudaGetSymbolAddress((void**)&wmTh, g_wmTh);

    cudaFuncSetAttribute(conv3x3_fp16,
                         cudaFuncAttributeMaxDynamicSharedMemorySize, SMEM_CONVH);
    cudaFuncSetAttribute(deconv_mask_fp16,
                         cudaFuncAttributeMaxDynamicSharedMemorySize, SMEM_FUSED);

    // prep: fp16 conversion + weight transposes
    f2h_fp16<<<25088, 256>>>(x, h0);
    transpose_w_fp16<<<dim3(64, 9, 4), 256>>>(Wc, wTh);
    transpose_wd_fp16<<<dim3(64, 1, 4), 256>>>(Wt, wdTh);
    transpose_wm_fp16<<<80, 256>>>(Wm, wmTh);

    // conv chain (fp16, unchanged)
    conv3x3_fp16<<<3136, 256, SMEM_CONVH>>>(h0, wTh + 0L * WLSTRIDE, bc + 0,   h1);
    conv3x3_fp16<<<3136, 256, SMEM_CONVH>>>(h1, wTh + 1L * WLSTRIDE, bc + 256, h0);
    conv3x3_fp16<<<3136, 256, SMEM_CONVH>>>(h0, wTh + 2L * WLSTRIDE, bc + 512, h1);
    conv3x3_fp16<<<3136, 256, SMEM_CONVH>>>(h1, wTh + 3L * WLSTRIDE, bc + 768, h0);

    // fused deconv + mask (z never leaves smem)
    deconv_mask_fp16<<<dim3(M_TOT / 64, 4), 256, SMEM_FUSED>>>(
        h0, wdTh, bt, wmTh, bm, out);
}

// round 17
// speedup vs baseline: 1.5181x; 1.5181x over previous
// ROIMaskHead fp16 pipeline v7: v6 + RACE FIX — tail commits empty cp.async
// groups so wait_group 2 always guarantees the consumed stage (conv + deconv).
#include <cuda_runtime.h>
#include <cuda_fp16.h>
#include <cstdint>

#define NROI 1024
#define M_TOT (NROI * 196)          // 200704
#define KTOT  2304
#define WLSTRIDE (256 * KTOT)

// Device-global scratch (allocation-free per harness rules)
__device__ __half g_h0[M_TOT * 256];
__device__ __half g_h1[M_TOT * 256];
__device__ __half g_wTh[4 * 256 * KTOT];     // conv W [layer][co][k]
__device__ __half g_wdTh[4 * 256 * 256];     // deconv W [parity][co][ci]
__device__ __half g_wmTh[80 * 256];          // mask W [cls][ci]
__device__ __half g_zh[4L * M_TOT * 256];    // deconv out, parity-major

// ---------------------------------------------------------------------------
__device__ __forceinline__ uint32_t smem_u32(const void* p) {
    uint32_t a;
    asm("{ .reg .u64 t; cvta.to.shared.u64 t, %1; cvt.u32.u64 %0, t; }"
        : "=r"(a) : "l"(p));
    return a;
}
__device__ __forceinline__ void cp16(uint32_t dst, const void* src, uint32_t bytes) {
    asm volatile("cp.async.cg.shared.global [%0], [%1], 16, %2;"
                 :: "r"(dst), "l"(src), "r"(bytes) : "memory");
}
#define LDSM4(r0, r1, r2, r3, addr) \
    asm volatile("ldmatrix.sync.aligned.m8n8.x4.shared.b16 {%0,%1,%2,%3}, [%4];" \
                 : "=r"(r0), "=r"(r1), "=r"(r2), "=r"(r3) : "r"(addr))

__device__ __forceinline__ void mma_f16(float c[4], const uint32_t a[4],
                                        uint32_t b0, uint32_t b1) {
    asm volatile(
        "mma.sync.aligned.m16n8k16.row.col.f32.f16.f16.f32 "
        "{%0,%1,%2,%3}, {%4,%5,%6,%7}, {%8,%9}, {%0,%1,%2,%3};"
        : "+f"(c[0]), "+f"(c[1]), "+f"(c[2]), "+f"(c[3])
        : "r"(a[0]), "r"(a[1]), "r"(a[2]), "r"(a[3]), "r"(b0), "r"(b1));
}

// ---------------------------------------------------------------------------
// Prep kernels
// ---------------------------------------------------------------------------
__global__ __launch_bounds__(256)
void f2h_fp16(const float* __restrict__ in, __half* __restrict__ out)
{
    long i = (long)(blockIdx.x * 256 + threadIdx.x) * 8;
    float4 v0 = *(const float4*)(in + i);
    float4 v1 = *(const float4*)(in + i + 4);
    __half2 h[4];
    h[0] = __floats2half2_rn(v0.x, v0.y);
    h[1] = __floats2half2_rn(v0.z, v0.w);
    h[2] = __floats2half2_rn(v1.x, v1.y);
    h[3] = __floats2half2_rn(v1.z, v1.w);
    *(uint4*)(out + i) = *(uint4*)h;
}

__global__ __launch_bounds__(256)
void transpose_w_fp16(const float* __restrict__ Wc, __half* __restrict__ wTh)
{
    __shared__ float ts[32][33];
    const int l  = blockIdx.z;
    const int kq = blockIdx.y;
    const int ci0 = (blockIdx.x >> 3) * 32;
    const int co0 = (blockIdx.x & 7) * 32;
    const int tx = threadIdx.x & 31, ty = threadIdx.x >> 5;
#pragma unroll
    for (int i = ty; i < 32; i += 8)
        ts[i][tx] = Wc[((l * 9 + kq) * 256 + ci0 + i) * 256 + co0 + tx];
    __syncthreads();
#pragma unroll
    for (int i = ty; i < 32; i += 8)
        wTh[(long)(l * 256 + co0 + i) * KTOT + kq * 256 + ci0 + tx] =
            __float2half_rn(ts[tx][i]);
}

__global__ __launch_bounds__(256)
void transpose_wd_fp16(const float* __restrict__ Wt, __half* __restrict__ wdTh)
{
    __shared__ float ts[32][33];
    const int ab  = blockIdx.z;
    const int ci0 = (blockIdx.x >> 3) * 32;
    const int co0 = (blockIdx.x & 7) * 32;
    const int tx = threadIdx.x & 31, ty = threadIdx.x >> 5;
    const float* src = Wt + (3 - ab) * 65536;   // Wt[1-a][1-b] (proven in R1)
#pragma unroll
    for (int i = ty; i < 32; i += 8)
        ts[i][tx] = src[(ci0 + i) * 256 + co0 + tx];
    __syncthreads();
#pragma unroll
    for (int i = ty; i < 32; i += 8)
        wdTh[ab * 65536 + (co0 + i) * 256 + ci0 + tx] = __float2half_rn(ts[tx][i]);
}

__global__ __launch_bounds__(256)
void transpose_wm_fp16(const float* __restrict__ Wm, __half* __restrict__ wmTh)
{
    int i = blockIdx.x * 256 + threadIdx.x;
    if (i < 80 * 256) {
        int cls = i >> 8, ci = i & 255;
        wmTh[i] = __float2half_rn(Wm[ci * 80 + cls]);
    }
}

// ---------------------------------------------------------------------------
// Conv 3x3 SAME (256->256) + bias + ReLU, fp16 mma.m16n8k16.
// 4-stage cp.async, 1 sync/iter; tail now commits EMPTY groups past the end
// so wait_group 2 always covers the consumed stage (race fix).
// ---------------------------------------------------------------------------
#define HSTAGE (128 * 40 * 2)                // 10240 B per tile (A or B)
#define NSTAGE 4
#define STG_BYTES (2 * HSTAGE)               // A+B per stage = 20480
#define SMEM_CONVH (NSTAGE * STG_BYTES + 1024)   // 82944 B

__global__ __launch_bounds__(256, 2)
void conv3x3_fp16(const __half* __restrict__ in,
                  const __half* __restrict__ wTh,
                  const float* __restrict__ bias,
                  __half* __restrict__ out)
{
    extern __shared__ char smem[];
    const uint32_t sb = smem_u32(smem);
    float* bias_s = (float*)(smem + NSTAGE * STG_BYTES);

    const int t = threadIdx.x, wid = t >> 5, lane = t & 31;
    const int bid = blockIdx.x;
    const int m0 = (bid >> 1) * 128;
    const int n0 = (bid & 1) * 128;
    const int warpM = (wid & 1) * 64;
    const int warpN = (wid >> 1) * 32;

    if (t < 32) ((float4*)bias_s)[t] = ((const float4*)(bias + n0))[t];

    int ahh[2], aww[2]; long abase[2];
    uint32_t adst[2], bdst[2];
    const __half* bsrc[2];
#pragma unroll
    for (int s = 0; s < 2; ++s) {
        int id  = t + s * 256;
        int row = id >> 2;
        int cq  = id & 3;
        int m = m0 + row;
        int n = m / 196;
        int pp = m - n * 196;
        int hh = pp / 14;
        ahh[s] = hh; aww[s] = pp - hh * 14;
        abase[s] = (long)n * 50176 + cq * 8;
        adst[s] = sb + row * 80 + cq * 16;
        bsrc[s] = wTh + (long)(n0 + row) * KTOT + cq * 8;
        bdst[s] = sb + HSTAGE + row * 80 + cq * 16;
    }

    float c[4][4][4];
#pragma unroll
    for (int i = 0; i < 4; ++i)
#pragma unroll
        for (int j = 0; j < 4; ++j)
#pragma unroll
            for (int q = 0; q < 4; ++q) c[i][j][q] = 0.f;

    auto load_tile = [&](int kt, int p) {
        const int kq = kt >> 3, ci0 = (kt & 7) << 5;
        const int kh = kq / 3, kw = kq - kh * 3;
        const uint32_t off = p * STG_BYTES;
#pragma unroll
        for (int s = 0; s < 2; ++s) {
            int ih = ahh[s] + kh - 1, iw = aww[s] + kw - 1;
            bool ok = ((unsigned)ih < 14u) & ((unsigned)iw < 14u);
            int ihc = ok ? ih : 0, iwc = ok ? iw : 0;
            cp16(adst[s] + off, in + abase[s] + (ihc * 14 + iwc) * 256 + ci0,
                 ok ? 16u : 0u);
        }
#pragma unroll
        for (int s = 0; s < 2; ++s)
            cp16(bdst[s] + off, bsrc[s] + kt * 32, 16u);
        asm volatile("cp.async.commit_group;" ::: "memory");
    };

    const int lr = (lane & 7) + ((lane >> 3) & 1) * 8;
    const int lk = (lane >> 4) * 8;

    load_tile(0, 0);
    load_tile(1, 1);
    load_tile(2, 2);

    for (int kt = 0; kt < 72; ++kt) {
        const int p = kt & (NSTAGE - 1);
        asm volatile("cp.async.wait_group %0;" :: "n"(NSTAGE - 2) : "memory");
        __syncthreads();

        const uint32_t Ab = sb + p * STG_BYTES;
        const uint32_t Bb = Ab + HSTAGE;
#pragma unroll
        for (int ks = 0; ks < 2; ++ks) {
            const int kc = ks * 16 + lk;
            uint32_t a[4][4], bq[2][4];
#pragma unroll
            for (int i = 0; i < 4; ++i)
                LDSM4(a[i][0], a[i][1], a[i][2], a[i][3],
                      Ab + (warpM + i * 16 + lr) * 80 + kc * 2);
#pragma unroll
            for (int j2 = 0; j2 < 2; ++j2)
                LDSM4(bq[j2][0], bq[j2][1], bq[j2][2], bq[j2][3],
                      Bb + (warpN + j2 * 16 + lr) * 80 + kc * 2);
#pragma unroll
            for (int i = 0; i < 4; ++i)
#pragma unroll
                for (int j = 0; j < 4; ++j) {
                    const int j2 = j >> 1, hi = j & 1;
                    mma_f16(c[i][j], a[i], bq[j2][hi], bq[j2][hi + 2]);
                }
        }
        // RACE FIX: always commit a group (empty past the end) so the
        // committed count tracks kt and wait_group 2 covers stage kt.
        if (kt + NSTAGE - 1 < 72)
            load_tile(kt + NSTAGE - 1, (kt + NSTAGE - 1) & (NSTAGE - 1));
        else
            asm volatile("cp.async.commit_group;" ::: "memory");
    }

#pragma unroll
    for (int j = 0; j < 4; ++j) {
        const int col = warpN + j * 8 + (lane & 3) * 2;
        const float b0 = bias_s[col], b1 = bias_s[col + 1];
#pragma unroll
        for (int i = 0; i < 4; ++i) {
            long r0 = m0 + warpM + i * 16 + (lane >> 2);
            __half2 h0 = __floats2half2_rn(fmaxf(c[i][j][0] + b0, 0.f),
                                           fmaxf(c[i][j][1] + b1, 0.f));
            __half2 h1 = __floats2half2_rn(fmaxf(c[i][j][2] + b0, 0.f),
                                           fmaxf(c[i][j][3] + b1, 0.f));
            *(__half2*)&out[(r0 << 8) + n0 + col]       = h0;
            *(__half2*)&out[((r0 + 8) << 8) + n0 + col] = h1;
        }
    }
}

// ---------------------------------------------------------------------------
// D1: deconv GEMM per parity, fp16. 4-stage/1-sync pipeline with the same
// empty-commit race fix; linearized A-sharing grid.
// bid decode: ab = bid&3, n0 = ((bid>>2)&1)*128, m0 = (bid>>3)*128.
// ---------------------------------------------------------------------------
__global__ __launch_bounds__(256, 2)
void deconv_fp16(const __half* __restrict__ y,
                 const __half* __restrict__ wdTh,
                 const float* __restrict__ bt,
                 __half* __restrict__ z)
{
    extern __shared__ char smem[];
    const uint32_t sb = smem_u32(smem);
    float* bias_s = (float*)(smem + NSTAGE * STG_BYTES);

    const int t = threadIdx.x, wid = t >> 5, lane = t & 31;
    const int bid = blockIdx.x;
    const int ab = bid & 3;
    const int n0 = ((bid >> 2) & 1) * 128;
    const int m0 = (bid >> 3) * 128;
    const int warpM = (wid & 1) * 64;
    const int warpN = (wid >> 1) * 32;

    if (t < 32) ((float4*)bias_s)[t] = ((const float4*)(bt + n0))[t];

    uint32_t adst[2], bdst[2];
    const __half* asrc[2];
    const __half* bsrc[2];
#pragma unroll
    for (int s = 0; s < 2; ++s) {
        int id  = t + s * 256;
        int row = id >> 2;
        int cq  = id & 3;
        asrc[s] = y + (long)(m0 + row) * 256 + cq * 8;
        adst[s] = sb + row * 80 + cq * 16;
        bsrc[s] = wdTh + ab * 65536 + (n0 + row) * 256 + cq * 8;
        bdst[s] = sb + HSTAGE + row * 80 + cq * 16;
    }

    float c[4][4][4];
#pragma unroll
    for (int i = 0; i < 4; ++i)
#pragma unroll
        for (int j = 0; j < 4; ++j)
#pragma unroll
            for (int q = 0; q < 4; ++q) c[i][j][q] = 0.f;

    auto load_tile = [&](int kt, int p) {
        const uint32_t off = p * STG_BYTES;
#pragma unroll
        for (int s = 0; s < 2; ++s) cp16(adst[s] + off, asrc[s] + kt * 32, 16u);
#pragma unroll
        for (int s = 0; s < 2; ++s) cp16(bdst[s] + off, bsrc[s] + kt * 32, 16u);
        asm volatile("cp.async.commit_group;" ::: "memory");
    };

    const int lr = (lane & 7) + ((lane >> 3) & 1) * 8;
    const int lk = (lane >> 4) * 8;

    load_tile(0, 0);
    load_tile(1, 1);
    load_tile(2, 2);

    for (int kt = 0; kt < 8; ++kt) {
        const int p = kt & (NSTAGE - 1);
        asm volatile("cp.async.wait_group %0;" :: "n"(NSTAGE - 2) : "memory");
        __syncthreads();

        const uint32_t Ab = sb + p * STG_BYTES;
        const uint32_t Bb = Ab + HSTAGE;
#pragma unroll
        for (int ks = 0; ks < 2; ++ks) {
            const int kc = ks * 16 + lk;
            uint32_t a[4][4], bq[2][4];
#pragma unroll
            for (int i = 0; i < 4; ++i)
                LDSM4(a[i][0], a[i][1], a[i][2], a[i][3],
                      Ab + (warpM + i * 16 + lr) * 80 + kc * 2);
#pragma unroll
            for (int j2 = 0; j2 < 2; ++j2)
                LDSM4(bq[j2][0], bq[j2][1], bq[j2][2], bq[j2][3],
                      Bb + (warpN + j2 * 16 + lr) * 80 + kc * 2);
#pragma unroll
            for (int i = 0; i < 4; ++i)
#pragma unroll
                for (int j = 0; j < 4; ++j) {
                    const int j2 = j >> 1, hi = j & 1;
                    mma_f16(c[i][j], a[i], bq[j2][hi], bq[j2][hi + 2]);
                }
        }
        // RACE FIX: empty commit keeps committed count = kt+3.
        if (kt + NSTAGE - 1 < 8)
            load_tile(kt + NSTAGE - 1, (kt + NSTAGE - 1) & (NSTAGE - 1));
        else
            asm volatile("cp.async.commit_group;" ::: "memory");
    }

    __half* zout = z + (long)ab * M_TOT * 256;
#pragma unroll
    for (int j = 0; j < 4; ++j) {
        const int col = warpN + j * 8 + (lane & 3) * 2;
        const float b0 = bias_s[col], b1 = bias_s[col + 1];
#pragma unroll
        for (int i = 0; i < 4; ++i) {
            long r0 = m0 + warpM + i * 16 + (lane >> 2);
            __half2 h0 = __floats2half2_rn(fmaxf(c[i][j][0] + b0, 0.f),
                                           fmaxf(c[i][j][1] + b1, 0.f));
            __half2 h1 = __floats2half2_rn(fmaxf(c[i][j][2] + b0, 0.f),
                                           fmaxf(c[i][j][3] + b1, 0.f));
            *(__half2*)&zout[(r0 << 8) + n0 + col]       = h0;
            *(__half2*)&zout[((r0 + 8) << 8) + n0 + col] = h1;
        }
    }
}

// ---------------------------------------------------------------------------
// D2: mask GEMM fp16 (unchanged 2-stage/2-sync — its wait_group 1/0 pairing
// is exact, no race)
// ---------------------------------------------------------------------------
#define MB_STAGE (80 * 40 * 2)                   // 6400 B
#define SMEM_MASK (2 * HSTAGE + 2 * MB_STAGE)    // 33280 B

__global__ __launch_bounds__(256, 2)
void mask_fp16(const __half* __restrict__ z,
               const __half* __restrict__ wmTh,
               const float* __restrict__ bm,
               float* __restrict__ out)
{
    extern __shared__ char smem[];
    const uint32_t sb = smem_u32(smem);
    const int t = threadIdx.x, wid = t >> 5, lane = t & 31;
    const long m0 = (long)blockIdx.x * 128;
    const int ab = (int)(m0 / M_TOT);
    const int aa = ab >> 1, bb = ab & 1;
    const int pix0 = (int)(m0 - (long)ab * M_TOT);

    uint32_t adst[2]; const __half* asrc[2];
#pragma unroll
    for (int s = 0; s < 2; ++s) {
        int id  = t + s * 256;
        int row = id >> 2;
        int cq  = id & 3;
        asrc[s] = z + (m0 + row) * 256 + cq * 8;
        adst[s] = sb + row * 80 + cq * 16;
    }

    float c[10][4];
#pragma unroll
    for (int j = 0; j < 10; ++j)
#pragma unroll
        for (int q = 0; q < 4; ++q) c[j][q] = 0.f;

    auto load_tile = [&](int kt, int p) {
#pragma unroll
        for (int s = 0; s < 2; ++s)
            cp16(adst[s] + p * HSTAGE, asrc[s] + kt * 32, 16u);
        for (int ch = t; ch < 320; ch += 256) {
            int row = ch >> 2, cq = ch & 3;
            cp16(sb + 2 * HSTAGE + p * MB_STAGE + row * 80 + cq * 16,
                 wmTh + row * 256 + kt * 32 + cq * 8, 16u);
        }
        asm volatile("cp.async.commit_group;" ::: "memory");
    };

    const int lr = (lane & 7) + ((lane >> 3) & 1) * 8;
    const int lk = (lane >> 4) * 8;

    load_tile(0, 0);

    for (int kt = 0; kt < 8; ++kt) {
        const int p = kt & 1;
        if (kt < 7) {
            load_tile(kt + 1, p ^ 1);
            asm volatile("cp.async.wait_group 1;" ::: "memory");
        } else {
            asm volatile("cp.async.wait_group 0;" ::: "memory");
        }
        __syncthreads();

        const uint32_t Ab = sb + p * HSTAGE;
        const uint32_t Bb = sb + 2 * HSTAGE + p * MB_STAGE;
#pragma unroll
        for (int ks = 0; ks < 2; ++ks) {
            const int kc = ks * 16 + lk;
            uint32_t a[4];
            LDSM4(a[0], a[1], a[2], a[3], Ab + (wid * 16 + lr) * 80 + kc * 2);
            uint32_t bq[5][4];
#pragma unroll
            for (int j2 = 0; j2 < 5; ++j2)
                LDSM4(bq[j2][0], bq[j2][1], bq[j2][2], bq[j2][3],
                      Bb + (j2 * 16 + lr) * 80 + kc * 2);
#pragma unroll
            for (int j = 0; j < 10; ++j) {
                const int j2 = j >> 1, hi = j & 1;
                mma_f16(c[j], a, bq[j2][hi], bq[j2][hi + 2]);
            }
        }
        __syncthreads();
    }

    float bmv[10][2];
#pragma unroll
    for (int j = 0; j < 10; ++j) {
        int col = j * 8 + (lane & 3) * 2;
        bmv[j][0] = bm[col]; bmv[j][1] = bm[col + 1];
    }

    int pixA = pix0 + wid * 16 + (lane >> 2);
    int pixB = pixA + 8;
    int nA = pixA / 196, pA = pixA - nA * 196, iiA = pA / 14, jjA = pA - iiA * 14;
    int nB = pixB / 196, pB = pixB - nB * 196, iiB = pB / 14, jjB = pB - iiB * 14;
    float* opA = out + ((long)(nA * 28 + iiA * 2 + aa) * 28 + jjA * 2 + bb) * 80;
    float* opB = out + ((long)(nB * 28 + iiB * 2 + aa) * 28 + jjB * 2 + bb) * 80;

#pragma unroll
    for (int j = 0; j < 10; ++j) {
        int col = j * 8 + (lane & 3) * 2;
        *(float2*)&opA[col] = make_float2(c[j][0] + bmv[j][0], c[j][1] + bmv[j][1]);
        *(float2*)&opB[col] = make_float2(c[j][2] + bmv[j][0], c[j][3] + bmv[j][1]);
    }
}

// ---------------------------------------------------------------------------
extern "C" void kernel_launch(void* const* d_in, const int* in_sizes, int n_in,
                              void* d_out, int out_size)
{
    const float* x  = (const float*)d_in[0];
    const float* Wc = (const float*)d_in[1];
    const float* bc = (const float*)d_in[2];
    const float* Wt = (const float*)d_in[3];
    const float* bt = (const float*)d_in[4];
    const float* Wm = (const float*)d_in[5];
    const float* bm = (const float*)d_in[6];
    float* out = (float*)d_out;

    __half *h0, *h1, *wTh, *wdTh, *wmTh, *zh;
    cudaGetSymbolAddress((void**)&h0,   g_h0);
    cudaGetSymbolAddress((void**)&h1,   g_h1);
    cudaGetSymbolAddress((void**)&wTh,  g_wTh);
    cudaGetSymbolAddress((void**)&wdTh, g_wdTh);
    cudaGetSymbolAddress((void**)&wmTh, g_wmTh);
    cudaGetSymbolAddress((void**)&zh,   g_zh);

    cudaFuncSetAttribute(conv3x3_fp16,
                         cudaFuncAttributeMaxDynamicSharedMemorySize, SMEM_CONVH);
    cudaFuncSetAttribute(deconv_fp16,
                         cudaFuncAttributeMaxDynamicSharedMemorySize, SMEM_CONVH);
    cudaFuncSetAttribute(mask_fp16,
                         cudaFuncAttributeMaxDynamicSharedMemorySize, SMEM_MASK);

    // prep: fp16 conversion + weight transposes
    f2h_fp16<<<25088, 256>>>(x, h0);
    transpose_w_fp16<<<dim3(64, 9, 4), 256>>>(Wc, wTh);
    transpose_wd_fp16<<<dim3(64, 1, 4), 256>>>(Wt, wdTh);
    transpose_wm_fp16<<<80, 256>>>(Wm, wmTh);

    // conv chain (fp16)
    conv3x3_fp16<<<3136, 256, SMEM_CONVH>>>(h0, wTh + 0L * WLSTRIDE, bc + 0,   h1);
    conv3x3_fp16<<<3136, 256, SMEM_CONVH>>>(h1, wTh + 1L * WLSTRIDE, bc + 256, h0);
    conv3x3_fp16<<<3136, 256, SMEM_CONVH>>>(h0, wTh + 2L * WLSTRIDE, bc + 512, h1);
    conv3x3_fp16<<<3136, 256, SMEM_CONVH>>>(h1, wTh + 3L * WLSTRIDE, bc + 768, h0);

    // deconv (linearized A-sharing grid) + mask
    deconv_fp16<<<12544, 256, SMEM_CONVH>>>(h0, wdTh, bt, zh);
    mask_fp16<<<4 * M_TOT / 128, 256, SMEM_MASK>>>(zh, wmTh, bm, out);
}